// round 5
// baseline (speedup 1.0000x reference)
#include <cuda_runtime.h>
#include <cuda_bf16.h>

#define FIVE_K 6
#define OUT_N  512
#define IN_N   1024
#define HID_N  32
#define B_N    256

typedef unsigned long long ull;

// ---------------------------------------------------------------------------
// f32x2 packed helpers (FFMA2 — ptxas never emits these from C++)
// ---------------------------------------------------------------------------
__device__ __forceinline__ ull pack2(float a, float b) {
    ull r;
    asm("mov.b64 %0, {%1, %2};"
        : "=l"(r) : "r"(__float_as_uint(a)), "r"(__float_as_uint(b)));
    return r;
}
__device__ __forceinline__ ull pdup(float a) {
    ull r;
    asm("mov.b64 %0, {%1, %1};" : "=l"(r) : "r"(__float_as_uint(a)));
    return r;
}
__device__ __forceinline__ void fma2(ull& d, ull a, ull b) {
    asm("fma.rn.f32x2 %0, %1, %2, %0;" : "+l"(d) : "l"(a), "l"(b));
}
__device__ __forceinline__ void unpack2(ull v, float& lo, float& hi) {
    unsigned ulo, uhi;
    asm("mov.b64 {%0, %1}, %2;" : "=r"(ulo), "=r"(uhi) : "l"(v));
    lo = __uint_as_float(ulo);
    hi = __uint_as_float(uhi);
}

// ---------------------------------------------------------------------------
// topk machinery: 64-bit keys (orderable_float << 10) | (1023 - idx)
// max key == argmax, ties toward smaller index. Pad key = 0 (< any real key).
// (identical to R4 — validated rel_err 0.0; do not modify)
// ---------------------------------------------------------------------------
__device__ __forceinline__ ull mk_key(float x, int gi) {
    unsigned u = __float_as_uint(x);
    unsigned ord = (u & 0x80000000u) ? ~u : (u | 0x80000000u);
    return ((ull)ord << 10) | (ull)(1023 - gi);
}
__device__ __forceinline__ void cas(ull& a, ull& b) {   // desc: a=max, b=min
    ull hi = a > b ? a : b;
    ull lo = a > b ? b : a;
    a = hi; b = lo;
}
__device__ __forceinline__ ull mx(ull a, ull b) { return a > b ? a : b; }

__device__ __forceinline__ void sort6(ull* t) {
    cas(t[0], t[1]); cas(t[2], t[3]); cas(t[4], t[5]);
    cas(t[0], t[2]); cas(t[1], t[3]);
    cas(t[1], t[2]);
    cas(t[0], t[4]); cas(t[1], t[5]);
    cas(t[2], t[4]); cas(t[3], t[5]);
    cas(t[1], t[2]); cas(t[3], t[4]);
}
__device__ __forceinline__ void merge6(ull* a, const ull* b) {
    ull t[6];
    t[0] = mx(a[0], b[5]); t[1] = mx(a[1], b[4]); t[2] = mx(a[2], b[3]);
    t[3] = mx(a[3], b[2]); t[4] = mx(a[4], b[1]); t[5] = mx(a[5], b[0]);
    sort6(t);
#pragma unroll
    for (int q = 0; q < 6; q++) a[q] = t[q];
}
__device__ __forceinline__ void sort4(ull& a0, ull& a1, ull& a2, ull& a3) {
    cas(a0, a1); cas(a2, a3); cas(a0, a2); cas(a1, a3); cas(a1, a2);
}

// ---------------------------------------------------------------------------
// One batch element through the 4-layer MLP (packed f32x2, single acc set).
// Keeps peak liveness at h[32] + acc[16 ull] ≈ 64 regs.
// ---------------------------------------------------------------------------
__device__ __forceinline__ float mlp_one(const float* __restrict__ sW1,
                                         const float* __restrict__ sW2,
                                         const float* __restrict__ sW3,
                                         const float* __restrict__ sW4,
                                         const float* x)
{
    float h[HID_N];
    ull acc[16];

    // layer 1: 6 -> 32
#pragma unroll
    for (int q = 0; q < 16; q++) acc[q] = 0ull;
#pragma unroll
    for (int r = 0; r < FIVE_K; r++) {
        const ulonglong2* wr = reinterpret_cast<const ulonglong2*>(sW1 + r * HID_N);
        ull d = pdup(x[r]);
#pragma unroll
        for (int q = 0; q < 8; q++) {
            ulonglong2 w = wr[q];
            fma2(acc[2 * q],     d, w.x);
            fma2(acc[2 * q + 1], d, w.y);
        }
    }
#pragma unroll
    for (int q = 0; q < 16; q++) {
        float lo, hi; unpack2(acc[q], lo, hi);
        h[2 * q]     = fmaxf(lo, 0.f);
        h[2 * q + 1] = fmaxf(hi, 0.f);
    }

    // layers 2 and 3: 32 -> 32, in place
    const float* Ws[2] = { sW2, sW3 };
#pragma unroll
    for (int L = 0; L < 2; L++) {
        const float* SW = Ws[L];
#pragma unroll
        for (int q = 0; q < 16; q++) acc[q] = 0ull;
#pragma unroll
        for (int r = 0; r < HID_N; r++) {
            const ulonglong2* wr = reinterpret_cast<const ulonglong2*>(SW + r * HID_N);
            ull d = pdup(h[r]);
#pragma unroll
            for (int q = 0; q < 8; q++) {
                ulonglong2 w = wr[q];
                fma2(acc[2 * q],     d, w.x);
                fma2(acc[2 * q + 1], d, w.y);
            }
        }
#pragma unroll
        for (int q = 0; q < 16; q++) {
            float lo, hi; unpack2(acc[q], lo, hi);
            h[2 * q]     = fmaxf(lo, 0.f);
            h[2 * q + 1] = fmaxf(hi, 0.f);
        }
    }

    // layer 4: 32 -> 1
    ull s = 0ull;
    const ull* w4p = reinterpret_cast<const ull*>(sW4);
#pragma unroll
    for (int p = 0; p < 16; p++)
        fma2(s, pack2(h[2 * p], h[2 * p + 1]), w4p[p]);
    float l0, l1;
    unpack2(s, l0, l1);
    return l0 + l1;
}

// ---------------------------------------------------------------------------
// Fused kernel: one block (128 threads) per output unit o.
// Thread t handles batch elements t and t+128, processed SEQUENTIALLY so only
// one activation/accumulator set is live (regs ~90 -> 5 blocks/SM).
// ---------------------------------------------------------------------------
__global__ __launch_bounds__(128, 5)
void blayer_fused(const float* __restrict__ inputs,
                  const float* __restrict__ mask,
                  const float* __restrict__ W1,
                  const float* __restrict__ W2,
                  const float* __restrict__ W3,
                  const float* __restrict__ W4,
                  float* __restrict__ out)
{
    __shared__ float sW1[FIVE_K * HID_N];
    __shared__ float sW2[HID_N * HID_N];
    __shared__ float sW3[HID_N * HID_N];
    __shared__ float sW4[HID_N];
    __shared__ ull   sLists[4][6];
    __shared__ int   sIdx[FIVE_K];

    const int o    = blockIdx.x;
    const int tid  = threadIdx.x;
    const int warp = tid >> 5;
    const int lane = tid & 31;

    // -- prefetch dense weights into registers (latency hides under topk) --
    const float4* w2g = reinterpret_cast<const float4*>(W2 + o * HID_N * HID_N);
    const float4* w3g = reinterpret_cast<const float4*>(W3 + o * HID_N * HID_N);
    float4 r2a = w2g[tid], r2b = w2g[tid + 128];
    float4 r3a = w3g[tid], r3b = w3g[tid + 128];
    float  w4r = (tid < HID_N) ? W4[o * HID_N + tid] : 0.f;

    // -- cooperative top-6: 8 mask values per thread --
    const float4* mk4 = reinterpret_cast<const float4*>(mask + o * IN_N);
    float4 m0 = mk4[tid], m1 = mk4[tid + 128];

    ull a[6], b[6];
    {
        ull k0 = mk_key(m0.x, 4 * tid + 0);
        ull k1 = mk_key(m0.y, 4 * tid + 1);
        ull k2 = mk_key(m0.z, 4 * tid + 2);
        ull k3 = mk_key(m0.w, 4 * tid + 3);
        ull k4 = mk_key(m1.x, 4 * (tid + 128) + 0);
        ull k5 = mk_key(m1.y, 4 * (tid + 128) + 1);
        ull k6 = mk_key(m1.z, 4 * (tid + 128) + 2);
        ull k7 = mk_key(m1.w, 4 * (tid + 128) + 3);
        sort4(k0, k1, k2, k3);
        sort4(k4, k5, k6, k7);
        a[0] = k0; a[1] = k1; a[2] = k2; a[3] = k3; a[4] = 0; a[5] = 0;
        b[0] = k4; b[1] = k5; b[2] = k6; b[3] = k7; b[4] = 0; b[5] = 0;
        merge6(a, b);
    }
#pragma unroll
    for (int off = 16; off >= 1; off >>= 1) {
#pragma unroll
        for (int j = 0; j < 6; j++)
            b[j] = __shfl_xor_sync(0xFFFFFFFFu, a[j], off);
        merge6(a, b);
    }
    if (lane == 0) {
#pragma unroll
        for (int j = 0; j < 6; j++) sLists[warp][j] = a[j];
    }

    // -- stage dense weights to smem --
    reinterpret_cast<float4*>(sW2)[tid]       = r2a;
    reinterpret_cast<float4*>(sW2)[tid + 128] = r2b;
    reinterpret_cast<float4*>(sW3)[tid]       = r3a;
    reinterpret_cast<float4*>(sW3)[tid + 128] = r3b;
    if (tid < HID_N) sW4[tid] = w4r;
    __syncthreads();

    // -- warp 0 merges the 4 warp lists --
    if (warp == 0) {
#pragma unroll
        for (int w = 1; w < 4; w++) {
#pragma unroll
            for (int j = 0; j < 6; j++) b[j] = sLists[w][j];
            merge6(a, b);
        }
        if (lane == 0) {
#pragma unroll
            for (int j = 0; j < 6; j++)
                sIdx[j] = 1023 - (int)(a[j] & 1023ull);
        }
    }
    __syncthreads();

    // -- gather W1 rows + the 6 input values for my two batch elements --
    int idx[FIVE_K];
#pragma unroll
    for (int j = 0; j < FIVE_K; j++) idx[j] = sIdx[j];

#pragma unroll
    for (int t = tid; t < FIVE_K * HID_N; t += 128) {
        int j = t >> 5, k = t & 31;
        sW1[t] = W1[(o * IN_N + sIdx[j]) * HID_N + k];
    }
    float xA[FIVE_K], xB[FIVE_K];
#pragma unroll
    for (int j = 0; j < FIVE_K; j++) {
        xA[j] = inputs[tid * IN_N + idx[j]];
        xB[j] = inputs[(tid + 128) * IN_N + idx[j]];
    }
    __syncthreads();

    // -- MLP: elem A fully, then elem B (one live acc/h set at a time) --
    float zA = mlp_one(sW1, sW2, sW3, sW4, xA);
    out[tid * OUT_N + o] = (zA >= 0.f) ? 1.f : -1.f;

    float zB = mlp_one(sW1, sW2, sW3, sW4, xB);
    out[(tid + 128) * OUT_N + o] = (zB >= 0.f) ? 1.f : -1.f;
}

// ---------------------------------------------------------------------------
extern "C" void kernel_launch(void* const* d_in, const int* in_sizes, int n_in,
                              void* d_out, int out_size)
{
    const float* inputs = (const float*)d_in[0];  // (B, IN)
    const float* mask   = (const float*)d_in[1];  // (OUT, IN)
    const float* W1     = (const float*)d_in[2];  // (OUT, IN, HID)
    const float* W2     = (const float*)d_in[3];  // (OUT, HID, HID)
    const float* W3     = (const float*)d_in[4];  // (OUT, HID, HID)
    const float* W4     = (const float*)d_in[5];  // (OUT, HID, 1)
    float* out = (float*)d_out;                   // (B, OUT)

    blayer_fused<<<OUT_N, 128>>>(inputs, mask, W1, W2, W3, W4, out);
}

// round 6
// speedup vs baseline: 1.5560x; 1.5560x over previous
#include <cuda_runtime.h>
#include <cuda_bf16.h>

#define FIVE_K 6
#define OUT_N  512
#define IN_N   1024
#define HID_N  32
#define B_N    256

typedef unsigned long long ull;

// ---------------------------------------------------------------------------
// f32x2 packed helpers (FFMA2 — ptxas never emits these from C++)
// ---------------------------------------------------------------------------
__device__ __forceinline__ ull pack2(float a, float b) {
    ull r;
    asm("mov.b64 %0, {%1, %2};"
        : "=l"(r) : "r"(__float_as_uint(a)), "r"(__float_as_uint(b)));
    return r;
}
__device__ __forceinline__ ull pdup(float a) {
    ull r;
    asm("mov.b64 %0, {%1, %1};" : "=l"(r) : "r"(__float_as_uint(a)));
    return r;
}
__device__ __forceinline__ void fma2(ull& d, ull a, ull b) {
    asm("fma.rn.f32x2 %0, %1, %2, %0;" : "+l"(d) : "l"(a), "l"(b));
}
__device__ __forceinline__ void unpack2(ull v, float& lo, float& hi) {
    unsigned ulo, uhi;
    asm("mov.b64 {%0, %1}, %2;" : "=r"(ulo), "=r"(uhi) : "l"(v));
    lo = __uint_as_float(ulo);
    hi = __uint_as_float(uhi);
}

// ---------------------------------------------------------------------------
// topk machinery: 64-bit keys (orderable_float << 10) | (1023 - idx)
// max key == argmax, ties toward smaller index. Pad key = 0 (< any real key).
// (validated rel_err 0.0 in R4 — unchanged)
// ---------------------------------------------------------------------------
__device__ __forceinline__ ull mk_key(float x, int gi) {
    unsigned u = __float_as_uint(x);
    unsigned ord = (u & 0x80000000u) ? ~u : (u | 0x80000000u);
    return ((ull)ord << 10) | (ull)(1023 - gi);
}
__device__ __forceinline__ void cas(ull& a, ull& b) {   // desc: a=max, b=min
    ull hi = a > b ? a : b;
    ull lo = a > b ? b : a;
    a = hi; b = lo;
}
__device__ __forceinline__ ull mx(ull a, ull b) { return a > b ? a : b; }

__device__ __forceinline__ void sort6(ull* t) {
    cas(t[0], t[1]); cas(t[2], t[3]); cas(t[4], t[5]);
    cas(t[0], t[2]); cas(t[1], t[3]);
    cas(t[1], t[2]);
    cas(t[0], t[4]); cas(t[1], t[5]);
    cas(t[2], t[4]); cas(t[3], t[5]);
    cas(t[1], t[2]); cas(t[3], t[4]);
}
__device__ __forceinline__ void merge6(ull* a, const ull* b) {
    ull t[6];
    t[0] = mx(a[0], b[5]); t[1] = mx(a[1], b[4]); t[2] = mx(a[2], b[3]);
    t[3] = mx(a[3], b[2]); t[4] = mx(a[4], b[1]); t[5] = mx(a[5], b[0]);
    sort6(t);
#pragma unroll
    for (int q = 0; q < 6; q++) a[q] = t[q];
}
__device__ __forceinline__ void sort4(ull& a0, ull& a1, ull& a2, ull& a3) {
    cas(a0, a1); cas(a2, a3); cas(a0, a2); cas(a1, a3); cas(a1, a2);
}

// ---------------------------------------------------------------------------
// Fused kernel: TWO blocks (128 threads) per output unit o; block handles
// half the batch, one element per thread. Per-thread liveness stays at
// h[32] + acc[16 ull] ~= 80-90 regs -> 5 blocks/SM, no spills.
// ---------------------------------------------------------------------------
__global__ __launch_bounds__(128, 5)
void blayer_fused(const float* __restrict__ inputs,
                  const float* __restrict__ mask,
                  const float* __restrict__ W1,
                  const float* __restrict__ W2,
                  const float* __restrict__ W3,
                  const float* __restrict__ W4,
                  float* __restrict__ out)
{
    __shared__ float sW1[FIVE_K * HID_N];
    __shared__ float sW2[HID_N * HID_N];
    __shared__ float sW3[HID_N * HID_N];
    __shared__ float sW4[HID_N];
    __shared__ ull   sLists[4][6];
    __shared__ int   sIdx[FIVE_K];

    const int o    = blockIdx.x >> 1;
    const int b    = ((blockIdx.x & 1) << 7) + threadIdx.x;  // my batch element
    const int tid  = threadIdx.x;
    const int warp = tid >> 5;
    const int lane = tid & 31;

    // -- prefetch dense weights into registers (latency hides under topk) --
    const float4* w2g = reinterpret_cast<const float4*>(W2 + o * HID_N * HID_N);
    const float4* w3g = reinterpret_cast<const float4*>(W3 + o * HID_N * HID_N);
    float4 r2a = w2g[tid], r2b = w2g[tid + 128];
    float4 r3a = w3g[tid], r3b = w3g[tid + 128];
    float  w4r = (tid < HID_N) ? W4[o * HID_N + tid] : 0.f;

    // -- cooperative top-6 of mask row o: 8 values per thread --
    const float4* mk4 = reinterpret_cast<const float4*>(mask + o * IN_N);
    float4 m0 = mk4[tid], m1 = mk4[tid + 128];

    ull a[6], bl[6];
    {
        ull k0 = mk_key(m0.x, 4 * tid + 0);
        ull k1 = mk_key(m0.y, 4 * tid + 1);
        ull k2 = mk_key(m0.z, 4 * tid + 2);
        ull k3 = mk_key(m0.w, 4 * tid + 3);
        ull k4 = mk_key(m1.x, 4 * (tid + 128) + 0);
        ull k5 = mk_key(m1.y, 4 * (tid + 128) + 1);
        ull k6 = mk_key(m1.z, 4 * (tid + 128) + 2);
        ull k7 = mk_key(m1.w, 4 * (tid + 128) + 3);
        sort4(k0, k1, k2, k3);
        sort4(k4, k5, k6, k7);
        a[0]  = k0; a[1]  = k1; a[2]  = k2; a[3]  = k3; a[4]  = 0; a[5]  = 0;
        bl[0] = k4; bl[1] = k5; bl[2] = k6; bl[3] = k7; bl[4] = 0; bl[5] = 0;
        merge6(a, bl);
    }
#pragma unroll
    for (int off = 16; off >= 1; off >>= 1) {
#pragma unroll
        for (int j = 0; j < 6; j++)
            bl[j] = __shfl_xor_sync(0xFFFFFFFFu, a[j], off);
        merge6(a, bl);
    }
    if (lane == 0) {
#pragma unroll
        for (int j = 0; j < 6; j++) sLists[warp][j] = a[j];
    }

    // -- stage dense weights to smem --
    reinterpret_cast<float4*>(sW2)[tid]       = r2a;
    reinterpret_cast<float4*>(sW2)[tid + 128] = r2b;
    reinterpret_cast<float4*>(sW3)[tid]       = r3a;
    reinterpret_cast<float4*>(sW3)[tid + 128] = r3b;
    if (tid < HID_N) sW4[tid] = w4r;
    __syncthreads();

    // -- warp 0 merges the 4 warp lists --
    if (warp == 0) {
#pragma unroll
        for (int w = 1; w < 4; w++) {
#pragma unroll
            for (int j = 0; j < 6; j++) bl[j] = sLists[w][j];
            merge6(a, bl);
        }
        if (lane == 0) {
#pragma unroll
            for (int j = 0; j < 6; j++)
                sIdx[j] = 1023 - (int)(a[j] & 1023ull);
        }
    }
    __syncthreads();

    // -- gather W1 rows + the 6 input values for my batch element --
#pragma unroll
    for (int t = tid; t < FIVE_K * HID_N; t += 128) {
        int j = t >> 5, k = t & 31;
        sW1[t] = W1[(o * IN_N + sIdx[j]) * HID_N + k];
    }
    float x[FIVE_K];
#pragma unroll
    for (int j = 0; j < FIVE_K; j++)
        x[j] = inputs[b * IN_N + sIdx[j]];
    __syncthreads();

    // ---------------- MLP: one element, packed f32x2 ----------------
    float h[HID_N];
    ull acc[16];

    // layer 1: 6 -> 32
#pragma unroll
    for (int q = 0; q < 16; q++) acc[q] = 0ull;
#pragma unroll
    for (int r = 0; r < FIVE_K; r++) {
        const ulonglong2* wr = reinterpret_cast<const ulonglong2*>(sW1 + r * HID_N);
        ull d = pdup(x[r]);
#pragma unroll
        for (int q = 0; q < 8; q++) {
            ulonglong2 w = wr[q];
            fma2(acc[2 * q],     d, w.x);
            fma2(acc[2 * q + 1], d, w.y);
        }
    }
#pragma unroll
    for (int q = 0; q < 16; q++) {
        float lo, hi; unpack2(acc[q], lo, hi);
        h[2 * q]     = fmaxf(lo, 0.f);
        h[2 * q + 1] = fmaxf(hi, 0.f);
    }

    // layer 2: 32 -> 32
#pragma unroll
    for (int q = 0; q < 16; q++) acc[q] = 0ull;
#pragma unroll
    for (int r = 0; r < HID_N; r++) {
        const ulonglong2* wr = reinterpret_cast<const ulonglong2*>(sW2 + r * HID_N);
        ull d = pdup(h[r]);
#pragma unroll
        for (int q = 0; q < 8; q++) {
            ulonglong2 w = wr[q];
            fma2(acc[2 * q],     d, w.x);
            fma2(acc[2 * q + 1], d, w.y);
        }
    }
#pragma unroll
    for (int q = 0; q < 16; q++) {
        float lo, hi; unpack2(acc[q], lo, hi);
        h[2 * q]     = fmaxf(lo, 0.f);
        h[2 * q + 1] = fmaxf(hi, 0.f);
    }

    // layer 3: 32 -> 32
#pragma unroll
    for (int q = 0; q < 16; q++) acc[q] = 0ull;
#pragma unroll
    for (int r = 0; r < HID_N; r++) {
        const ulonglong2* wr = reinterpret_cast<const ulonglong2*>(sW3 + r * HID_N);
        ull d = pdup(h[r]);
#pragma unroll
        for (int q = 0; q < 8; q++) {
            ulonglong2 w = wr[q];
            fma2(acc[2 * q],     d, w.x);
            fma2(acc[2 * q + 1], d, w.y);
        }
    }
#pragma unroll
    for (int q = 0; q < 16; q++) {
        float lo, hi; unpack2(acc[q], lo, hi);
        h[2 * q]     = fmaxf(lo, 0.f);
        h[2 * q + 1] = fmaxf(hi, 0.f);
    }

    // layer 4: 32 -> 1, sign (sigmoid(z) >= 0.5 <=> z >= 0)
    ull s = 0ull;
    const ull* w4p = reinterpret_cast<const ull*>(sW4);
#pragma unroll
    for (int p = 0; p < 16; p++)
        fma2(s, pack2(h[2 * p], h[2 * p + 1]), w4p[p]);
    float l0, l1;
    unpack2(s, l0, l1);
    float z = l0 + l1;

    out[b * OUT_N + o] = (z >= 0.f) ? 1.f : -1.f;
}

// ---------------------------------------------------------------------------
extern "C" void kernel_launch(void* const* d_in, const int* in_sizes, int n_in,
                              void* d_out, int out_size)
{
    const float* inputs = (const float*)d_in[0];  // (B, IN)
    const float* mask   = (const float*)d_in[1];  // (OUT, IN)
    const float* W1     = (const float*)d_in[2];  // (OUT, IN, HID)
    const float* W2     = (const float*)d_in[3];  // (OUT, HID, HID)
    const float* W3     = (const float*)d_in[4];  // (OUT, HID, HID)
    const float* W4     = (const float*)d_in[5];  // (OUT, HID, 1)
    float* out = (float*)d_out;                   // (B, OUT)

    blayer_fused<<<OUT_N * 2, 128>>>(inputs, mask, W1, W2, W3, W4, out);
}

// round 7
// speedup vs baseline: 1.6000x; 1.0282x over previous
#include <cuda_runtime.h>
#include <cuda_bf16.h>

#define FIVE_K 6
#define OUT_N  512
#define IN_N   1024
#define HID_N  32
#define B_N    256
#define HPAD   36   // padded stride (floats) for per-elem h region: conflict-free LDS.128

typedef unsigned long long ull;

// ---------------------------------------------------------------------------
// f32x2 packed helpers (FFMA2 — ptxas never emits these from C++)
// ---------------------------------------------------------------------------
__device__ __forceinline__ ull pack2(float a, float b) {
    ull r;
    asm("mov.b64 %0, {%1, %2};"
        : "=l"(r) : "r"(__float_as_uint(a)), "r"(__float_as_uint(b)));
    return r;
}
__device__ __forceinline__ ull pdup(float a) {
    ull r;
    asm("mov.b64 %0, {%1, %1};" : "=l"(r) : "r"(__float_as_uint(a)));
    return r;
}
__device__ __forceinline__ void fma2(ull& d, ull a, ull b) {
    asm("fma.rn.f32x2 %0, %1, %2, %0;" : "+l"(d) : "l"(a), "l"(b));
}
__device__ __forceinline__ void unpack2(ull v, float& lo, float& hi) {
    unsigned ulo, uhi;
    asm("mov.b64 {%0, %1}, %2;" : "=r"(ulo), "=r"(uhi) : "l"(v));
    lo = __uint_as_float(ulo);
    hi = __uint_as_float(uhi);
}

// ---------------------------------------------------------------------------
// topk machinery: 64-bit keys (orderable_float << 10) | (1023 - idx)
// (validated rel_err 0.0 since R4 — unchanged)
// ---------------------------------------------------------------------------
__device__ __forceinline__ ull mk_key(float x, int gi) {
    unsigned u = __float_as_uint(x);
    unsigned ord = (u & 0x80000000u) ? ~u : (u | 0x80000000u);
    return ((ull)ord << 10) | (ull)(1023 - gi);
}
__device__ __forceinline__ void cas(ull& a, ull& b) {
    ull hi = a > b ? a : b;
    ull lo = a > b ? b : a;
    a = hi; b = lo;
}
__device__ __forceinline__ ull mx(ull a, ull b) { return a > b ? a : b; }

__device__ __forceinline__ void sort6(ull* t) {
    cas(t[0], t[1]); cas(t[2], t[3]); cas(t[4], t[5]);
    cas(t[0], t[2]); cas(t[1], t[3]);
    cas(t[1], t[2]);
    cas(t[0], t[4]); cas(t[1], t[5]);
    cas(t[2], t[4]); cas(t[3], t[5]);
    cas(t[1], t[2]); cas(t[3], t[4]);
}
__device__ __forceinline__ void merge6(ull* a, const ull* b) {
    ull t[6];
    t[0] = mx(a[0], b[5]); t[1] = mx(a[1], b[4]); t[2] = mx(a[2], b[3]);
    t[3] = mx(a[3], b[2]); t[4] = mx(a[4], b[1]); t[5] = mx(a[5], b[0]);
    sort6(t);
#pragma unroll
    for (int q = 0; q < 6; q++) a[q] = t[q];
}
__device__ __forceinline__ void sort4(ull& a0, ull& a1, ull& a2, ull& a3) {
    cas(a0, a1); cas(a2, a3); cas(a0, a2); cas(a1, a3); cas(a1, a2);
}

// relu+pack acc pairs (outs 4qq..4qq+3) into a float4 for one STS.128
__device__ __forceinline__ float4 relu4(ull p0, ull p1) {
    float l0, h0, l1, h1;
    unpack2(p0, l0, h0);
    unpack2(p1, l1, h1);
    return make_float4(fmaxf(l0, 0.f), fmaxf(h0, 0.f),
                       fmaxf(l1, 0.f), fmaxf(h1, 0.f));
}

// ---------------------------------------------------------------------------
// Fused kernel: one block (128 threads) per unit o; thread t owns batch
// elements t and t+128 (E=2, weight LDS amortized over both). Activations
// live in per-thread PRIVATE smem regions (stride-36 floats: conflict-free
// LDS.128/STS.128) and are streamed in 8-float chunks, keeping register
// liveness ~110 -> 4 blocks/SM without spills. No syncthreads in the MLP.
// ---------------------------------------------------------------------------
__global__ __launch_bounds__(128, 4)
void blayer_fused(const float* __restrict__ inputs,
                  const float* __restrict__ mask,
                  const float* __restrict__ W1,
                  const float* __restrict__ W2,
                  const float* __restrict__ W3,
                  const float* __restrict__ W4,
                  float* __restrict__ out)
{
    __shared__ float sH[2 * 128 * HPAD];    // 36.9 KB activation parking
    __shared__ float sW1[FIVE_K * HID_N];
    __shared__ float sW2[HID_N * HID_N];
    __shared__ float sW3[HID_N * HID_N];
    __shared__ float sW4[HID_N];
    __shared__ ull   sLists[4][6];
    __shared__ int   sIdx[FIVE_K];

    const int o    = blockIdx.x;
    const int tid  = threadIdx.x;
    const int warp = tid >> 5;
    const int lane = tid & 31;

    // per-thread private h regions (float4 views). Lane word-stride = 36
    // -> bank group 4*lane mod 32: conflict-free for .128 accesses.
    float4* hA4 = reinterpret_cast<float4*>(sH) + tid * (HPAD / 4);
    float4* hB4 = reinterpret_cast<float4*>(sH) + (128 + tid) * (HPAD / 4);

    // -- prefetch dense weights into registers (latency hides under topk) --
    const float4* w2g = reinterpret_cast<const float4*>(W2 + o * HID_N * HID_N);
    const float4* w3g = reinterpret_cast<const float4*>(W3 + o * HID_N * HID_N);
    float4 r2a = w2g[tid], r2b = w2g[tid + 128];
    float4 r3a = w3g[tid], r3b = w3g[tid + 128];
    float  w4r = (tid < HID_N) ? W4[o * HID_N + tid] : 0.f;

    // -- cooperative top-6 of mask row o: 8 values per thread --
    const float4* mk4 = reinterpret_cast<const float4*>(mask + o * IN_N);
    float4 m0 = mk4[tid], m1 = mk4[tid + 128];

    ull a[6], bl[6];
    {
        ull k0 = mk_key(m0.x, 4 * tid + 0);
        ull k1 = mk_key(m0.y, 4 * tid + 1);
        ull k2 = mk_key(m0.z, 4 * tid + 2);
        ull k3 = mk_key(m0.w, 4 * tid + 3);
        ull k4 = mk_key(m1.x, 4 * (tid + 128) + 0);
        ull k5 = mk_key(m1.y, 4 * (tid + 128) + 1);
        ull k6 = mk_key(m1.z, 4 * (tid + 128) + 2);
        ull k7 = mk_key(m1.w, 4 * (tid + 128) + 3);
        sort4(k0, k1, k2, k3);
        sort4(k4, k5, k6, k7);
        a[0]  = k0; a[1]  = k1; a[2]  = k2; a[3]  = k3; a[4]  = 0; a[5]  = 0;
        bl[0] = k4; bl[1] = k5; bl[2] = k6; bl[3] = k7; bl[4] = 0; bl[5] = 0;
        merge6(a, bl);
    }
#pragma unroll
    for (int off = 16; off >= 1; off >>= 1) {
#pragma unroll
        for (int j = 0; j < 6; j++)
            bl[j] = __shfl_xor_sync(0xFFFFFFFFu, a[j], off);
        merge6(a, bl);
    }
    if (lane == 0) {
#pragma unroll
        for (int j = 0; j < 6; j++) sLists[warp][j] = a[j];
    }

    // -- stage dense weights to smem --
    reinterpret_cast<float4*>(sW2)[tid]       = r2a;
    reinterpret_cast<float4*>(sW2)[tid + 128] = r2b;
    reinterpret_cast<float4*>(sW3)[tid]       = r3a;
    reinterpret_cast<float4*>(sW3)[tid + 128] = r3b;
    if (tid < HID_N) sW4[tid] = w4r;
    __syncthreads();

    // -- warp 0 merges the 4 warp lists --
    if (warp == 0) {
#pragma unroll
        for (int w = 1; w < 4; w++) {
#pragma unroll
            for (int j = 0; j < 6; j++) bl[j] = sLists[w][j];
            merge6(a, bl);
        }
        if (lane == 0) {
#pragma unroll
            for (int j = 0; j < 6; j++)
                sIdx[j] = 1023 - (int)(a[j] & 1023ull);
        }
    }
    __syncthreads();

    // -- W1 rows + the 6 input values for my two batch elements --
#pragma unroll
    for (int t = tid; t < FIVE_K * HID_N; t += 128) {
        int j = t >> 5, k = t & 31;
        sW1[t] = W1[(o * IN_N + sIdx[j]) * HID_N + k];
    }
    float xA[FIVE_K], xB[FIVE_K];
#pragma unroll
    for (int j = 0; j < FIVE_K; j++) {
        int ix = sIdx[j];
        xA[j] = inputs[tid * IN_N + ix];
        xB[j] = inputs[(tid + 128) * IN_N + ix];
    }
    __syncthreads();

    ull accA[16], accB[16];

    // ---- layer 1: 6 -> 32, result parked in sH ----
#pragma unroll
    for (int q = 0; q < 16; q++) { accA[q] = 0ull; accB[q] = 0ull; }
#pragma unroll
    for (int r = 0; r < FIVE_K; r++) {
        const ulonglong2* wr = reinterpret_cast<const ulonglong2*>(sW1 + r * HID_N);
        ull dA = pdup(xA[r]), dB = pdup(xB[r]);
#pragma unroll
        for (int q = 0; q < 8; q++) {
            ulonglong2 w = wr[q];
            fma2(accA[2 * q],     dA, w.x);
            fma2(accA[2 * q + 1], dA, w.y);
            fma2(accB[2 * q],     dB, w.x);
            fma2(accB[2 * q + 1], dB, w.y);
        }
    }
#pragma unroll
    for (int qq = 0; qq < 8; qq++) {
        hA4[qq] = relu4(accA[2 * qq], accA[2 * qq + 1]);
        hB4[qq] = relu4(accB[2 * qq], accB[2 * qq + 1]);
    }

    // ---- layers 2 & 3: 32 -> 32, h streamed from sH in 8-float chunks ----
#pragma unroll
    for (int L = 0; L < 2; L++) {
        const float* SW = (L == 0) ? sW2 : sW3;
#pragma unroll
        for (int q = 0; q < 16; q++) { accA[q] = 0ull; accB[q] = 0ull; }
#pragma unroll
        for (int rb = 0; rb < 4; rb++) {
            float4 ca0 = hA4[rb * 2], ca1 = hA4[rb * 2 + 1];
            float4 cb0 = hB4[rb * 2], cb1 = hB4[rb * 2 + 1];
            float ha[8] = { ca0.x, ca0.y, ca0.z, ca0.w,
                            ca1.x, ca1.y, ca1.z, ca1.w };
            float hb[8] = { cb0.x, cb0.y, cb0.z, cb0.w,
                            cb1.x, cb1.y, cb1.z, cb1.w };
#pragma unroll
            for (int r8 = 0; r8 < 8; r8++) {
                const ulonglong2* wr = reinterpret_cast<const ulonglong2*>(
                    SW + (rb * 8 + r8) * HID_N);
                ull dA = pdup(ha[r8]), dB = pdup(hb[r8]);
#pragma unroll
                for (int q = 0; q < 8; q++) {
                    ulonglong2 w = wr[q];
                    fma2(accA[2 * q],     dA, w.x);
                    fma2(accA[2 * q + 1], dA, w.y);
                    fma2(accB[2 * q],     dB, w.x);
                    fma2(accB[2 * q + 1], dB, w.y);
                }
            }
        }
#pragma unroll
        for (int qq = 0; qq < 8; qq++) {
            hA4[qq] = relu4(accA[2 * qq], accA[2 * qq + 1]);
            hB4[qq] = relu4(accB[2 * qq], accB[2 * qq + 1]);
        }
    }

    // ---- layer 4: 32 -> 1, sign (sigmoid(z) >= 0.5 <=> z >= 0) ----
    ull sA = 0ull, sB = 0ull;
    const ulonglong2* w4p = reinterpret_cast<const ulonglong2*>(sW4);
#pragma unroll
    for (int rb = 0; rb < 4; rb++) {
        float4 ca0 = hA4[rb * 2], ca1 = hA4[rb * 2 + 1];
        float4 cb0 = hB4[rb * 2], cb1 = hB4[rb * 2 + 1];
        ulonglong2 w0 = w4p[rb * 2], w1 = w4p[rb * 2 + 1];
        fma2(sA, pack2(ca0.x, ca0.y), w0.x);
        fma2(sA, pack2(ca0.z, ca0.w), w0.y);
        fma2(sA, pack2(ca1.x, ca1.y), w1.x);
        fma2(sA, pack2(ca1.z, ca1.w), w1.y);
        fma2(sB, pack2(cb0.x, cb0.y), w0.x);
        fma2(sB, pack2(cb0.z, cb0.w), w0.y);
        fma2(sB, pack2(cb1.x, cb1.y), w1.x);
        fma2(sB, pack2(cb1.z, cb1.w), w1.y);
    }
    float l0, l1;
    unpack2(sA, l0, l1);
    float zA = l0 + l1;
    unpack2(sB, l0, l1);
    float zB = l0 + l1;

    out[tid * OUT_N + o]         = (zA >= 0.f) ? 1.f : -1.f;
    out[(tid + 128) * OUT_N + o] = (zB >= 0.f) ? 1.f : -1.f;
}

// ---------------------------------------------------------------------------
extern "C" void kernel_launch(void* const* d_in, const int* in_sizes, int n_in,
                              void* d_out, int out_size)
{
    const float* inputs = (const float*)d_in[0];  // (B, IN)
    const float* mask   = (const float*)d_in[1];  // (OUT, IN)
    const float* W1     = (const float*)d_in[2];  // (OUT, IN, HID)
    const float* W2     = (const float*)d_in[3];  // (OUT, HID, HID)
    const float* W3     = (const float*)d_in[4];  // (OUT, HID, HID)
    const float* W4     = (const float*)d_in[5];  // (OUT, HID, 1)
    float* out = (float*)d_out;                   // (B, OUT)

    // hint: maximize shared-memory carveout so 4 blocks/SM (4 x 45.9KB) fit.
    static bool attr_set = false;
    if (!attr_set) {
        cudaFuncSetAttribute(blayer_fused,
                             cudaFuncAttributePreferredSharedMemoryCarveout,
                             cudaSharedmemCarveoutMaxShared);
        attr_set = true;
    }

    blayer_fused<<<OUT_N, 128>>>(inputs, mask, W1, W2, W3, W4, out);
}